// round 9
// baseline (speedup 1.0000x reference)
#include <cuda_runtime.h>
#include <math.h>

#define NB 4096

// Per-box SAT data in smem: 2 float4 per box
//  v0 = (cx, cy, a0x, a0y)   center + edge vector 0
//  v1 = (a1x, a1y, L0, L1)   edge vector 1, L = |a|^2

// giou1d (only called when no axis separates, t_in > 0).
__device__ __forceinline__ float giou_slow(float La, float Lb, float S,
                                           float t_in, float d) {
    float th    = fmaf(0.5f, S, fabsf(d));
    float inter = fminf(fminf(La, Lb), t_in);   // > 0 here
    float hull  = fmaxf(fmaxf(La, Lb), th);
    float uni   = S - inter;
    float tmp   = fmaf(2.0f, inter, -S);        // inter - uni
    float N     = fmaf(uni, uni, tmp * hull);
    return __fdividef(N, uni * hull);
}

__global__ __launch_bounds__(256) void pair_kernel(
    const float* __restrict__ boxes, float* __restrict__ out)
{
    __shared__ float4 sI[32 * 2];
    __shared__ float4 sJ[64 * 2];
    __shared__ float  smT[64][33];     // [jloc][iloc], holds full tile result
    __shared__ unsigned short s_wl[2048];
    __shared__ int s_cnt;

    // linear bid -> (ct, rt) over tiles with rt <= 2*ct+1
    const int b = blockIdx.x;
    int ct = (int)(0.5f * (sqrtf(4.0f * (float)b + 1.0f) - 1.0f));
    if ((ct + 1) * (ct + 2) <= b) ct++;
    if (ct * (ct + 1) > b) ct--;
    const int rt = b - ct * (ct + 1);

    const int ti = rt * 32;
    const int tj = ct * 64;
    const int t  = threadIdx.x;

    if (t == 0) s_cnt = 0;

    // Build SAT data for this tile's 96 boxes
    if (t < 96) {
        const int isJ = (t >= 32);
        const int loc = isJ ? (t - 32) : t;
        const int gb  = isJ ? (tj + loc) : (ti + loc);
        const float* bp = boxes + gb * 5;
        float cx = bp[0], cy = bp[1], w = bp[2], h = bp[3], ang = bp[4];
        float s, c;
        __sincosf(ang, &s, &c);
        float4 v0 = make_float4(cx, cy, w * c, -w * s);
        float4 v1 = make_float4(h * s, h * c, w * w, h * h);
        if (isJ) { sJ[loc * 2] = v0; sJ[loc * 2 + 1] = v1; }
        else     { sI[loc * 2] = v0; sI[loc * 2 + 1] = v1; }
    }

    // zero-fill smT (2112 floats = 528 float4)
    {
        float4* z4 = (float4*)&smT[0][0];
        float4 zz = make_float4(0.f, 0.f, 0.f, 0.f);
        for (int k = t; k < 528; k += 256) z4[k] = zz;
    }
    __syncthreads();

    const int tx = t & 31;
    const int ty = t >> 5;
    const bool diagTile = (rt >= 2 * ct);

    float4 Ja[2], Jb[2];
#pragma unroll
    for (int jj = 0; jj < 2; jj++) {
        int jl = tx + jj * 32;
        Ja[jj] = sJ[jl * 2 + 0];
        Jb[jj] = sJ[jl * 2 + 1];
    }

    // ---- Phase 1: separation test only; compact potential overlaps ----
#pragma unroll
    for (int ii = 0; ii < 4; ii++) {
        const int iloc = ty * 4 + ii;
        const float4 Ia = sI[iloc * 2 + 0];
        const float4 Ib = sI[iloc * 2 + 1];

#pragma unroll
        for (int jj = 0; jj < 2; jj++) {
            const int jloc = tx + jj * 32;
            const float a0ix = Ia.z, a0iy = Ia.w, a1ix = Ib.x, a1iy = Ib.y;
            const float a0jx = Ja[jj].z, a0jy = Ja[jj].w;
            const float a1jx = Jb[jj].x, a1jy = Jb[jj].y;

            float dcx = Ja[jj].x - Ia.x;
            float dcy = Ja[jj].y - Ia.y;

            float M00 = fmaf(a0ix, a0jx, a0iy * a0jy);
            float M01 = fmaf(a0ix, a1jx, a0iy * a1jy);
            float M10 = fmaf(a1ix, a0jx, a1iy * a0jy);
            float M11 = fmaf(a1ix, a1jx, a1iy * a1jy);

            float dA0 = fmaf(dcx, a0ix, dcy * a0iy);
            float dA1 = fmaf(dcx, a1ix, dcy * a1iy);
            float dB0 = fmaf(dcx, a0jx, dcy * a0jy);
            float dB1 = fmaf(dcx, a1jx, dcy * a1jy);

            float S0 = Ib.z     + (fabsf(M00) + fabsf(M01));
            float S1 = Ib.w     + (fabsf(M10) + fabsf(M11));
            float S2 = Jb[jj].z + (fabsf(M00) + fabsf(M10));
            float S3 = Jb[jj].w + (fabsf(M01) + fabsf(M11));

            float t0 = fmaf(0.5f, S0, -fabsf(dA0));
            float t1 = fmaf(0.5f, S1, -fabsf(dA1));
            float t2 = fmaf(0.5f, S2, -fabsf(dB0));
            float t3 = fmaf(0.5f, S3, -fabsf(dB1));
            float m = fminf(fminf(t0, t1), fminf(t2, t3));

            bool push = (m > 0.0f);
            if (diagTile && (ti + iloc == tj + jloc)) push = false;

            unsigned msk = __ballot_sync(0xffffffffu, push);
            if (msk) {
                int leader = __ffs(msk) - 1;
                int base = 0;
                if (tx == leader) base = atomicAdd(&s_cnt, __popc(msk));
                base = __shfl_sync(0xffffffffu, base, leader);
                if (push) {
                    int pos = base + __popc(msk & ((1u << tx) - 1u));
                    s_wl[pos] = (unsigned short)(iloc | (jloc << 8));
                }
            }
        }
    }
    __syncthreads();

    // ---- Phase 2: dense giou on compacted worklist ----
    const int cnt = s_cnt;
    for (int k = t; k < cnt; k += 256) {
        const int e = s_wl[k];
        const int iloc = e & 255;
        const int jloc = e >> 8;
        const float4 Ia = sI[iloc * 2 + 0];
        const float4 Ib = sI[iloc * 2 + 1];
        const float4 Jav = sJ[jloc * 2 + 0];
        const float4 Jbv = sJ[jloc * 2 + 1];

        const float a0ix = Ia.z, a0iy = Ia.w, a1ix = Ib.x, a1iy = Ib.y;
        const float a0jx = Jav.z, a0jy = Jav.w, a1jx = Jbv.x, a1jy = Jbv.y;

        float dcx = Jav.x - Ia.x;
        float dcy = Jav.y - Ia.y;

        float M00 = fmaf(a0ix, a0jx, a0iy * a0jy);
        float M01 = fmaf(a0ix, a1jx, a0iy * a1jy);
        float M10 = fmaf(a1ix, a0jx, a1iy * a0jy);
        float M11 = fmaf(a1ix, a1jx, a1iy * a1jy);

        float dA0 = fmaf(dcx, a0ix, dcy * a0iy);
        float dA1 = fmaf(dcx, a1ix, dcy * a1iy);
        float dB0 = fmaf(dcx, a0jx, dcy * a0jy);
        float dB1 = fmaf(dcx, a1jx, dcy * a1jy);

        float LbA0 = fabsf(M00) + fabsf(M01);
        float LbA1 = fabsf(M10) + fabsf(M11);
        float LbB0 = fabsf(M00) + fabsf(M10);
        float LbB1 = fabsf(M01) + fabsf(M11);

        float S0 = Ib.z  + LbA0;
        float S1 = Ib.w  + LbA1;
        float S2 = Jbv.z + LbB0;
        float S3 = Jbv.w + LbB1;

        float t0 = fmaf(0.5f, S0, -fabsf(dA0));
        float t1 = fmaf(0.5f, S1, -fabsf(dA1));
        float t2 = fmaf(0.5f, S2, -fabsf(dB0));
        float t3 = fmaf(0.5f, S3, -fabsf(dB1));

        float g0 = giou_slow(Ib.z,  LbA0, S0, t0, dA0);
        float g1 = giou_slow(Ib.w,  LbA1, S1, t1, dA1);
        float g2 = giou_slow(Jbv.z, LbB0, S2, t2, dB0);
        float g3 = giou_slow(Jbv.w, LbB1, S3, t3, dB1);

        float res = fmaxf(fminf(fminf(g0, g1), fminf(g2, g3)), 0.0f);
        smT[jloc][iloc] = res;
    }
    __syncthreads();

    // ---- Write-back ----
    // normal rows: out[ti+r][tj + c0 .. c0+7], 2x STG.128 per thread
    {
        const int r  = t >> 3;        // 0..31
        const int c0 = (t & 7) * 8;   // 0..56
        float v[8];
#pragma unroll
        for (int k = 0; k < 8; k++) v[k] = smT[c0 + k][r];
        float4* p = (float4*)(out + (size_t)(ti + r) * NB + tj + c0);
        p[0] = make_float4(v[0], v[1], v[2], v[3]);
        p[1] = make_float4(v[4], v[5], v[6], v[7]);
    }
    // mirror rows: out[tj+r][ti + c0 .. c0+7]
    {
        const int r  = t >> 2;        // 0..63
        const int c0 = (t & 3) * 8;   // 0..24
        float v[8];
#pragma unroll
        for (int k = 0; k < 8; k++) v[k] = smT[r][c0 + k];
        float4* p = (float4*)(out + (size_t)(tj + r) * NB + ti + c0);
        p[0] = make_float4(v[0], v[1], v[2], v[3]);
        p[1] = make_float4(v[4], v[5], v[6], v[7]);
    }
}

extern "C" void kernel_launch(void* const* d_in, const int* in_sizes, int n_in,
                              void* d_out, int out_size) {
    const float* boxes = (const float*)d_in[0];
    float* out = (float*)d_out;
    (void)in_sizes; (void)n_in; (void)out_size;

    pair_kernel<<<4160, 256>>>(boxes, out);
}

// round 12
// speedup vs baseline: 1.3489x; 1.3489x over previous
#include <cuda_runtime.h>
#include <math.h>

#define NB 4096

// Per-box SAT data in smem: 2 float4 per box
//  v0 = (cx, cy, a0x, a0y)   center + edge vector 0
//  v1 = (a1x, a1y, L0, L1)   edge vector 1, L = |a|^2

// giou1d, called only when no axis separates (t_in > 0).
__device__ __forceinline__ float giou_slow(float La, float Lb, float S,
                                           float t_in, float d) {
    float th    = fmaf(0.5f, S, fabsf(d));
    float inter = fminf(fminf(La, Lb), t_in);   // > 0 here
    float hull  = fmaxf(fmaxf(La, Lb), th);
    float uni   = S - inter;
    float tmp   = fmaf(2.0f, inter, -S);        // inter - uni
    float N     = fmaf(uni, uni, tmp * hull);
    return __fdividef(N, uni * hull);
}

__global__ __launch_bounds__(256) void pair_kernel(
    const float* __restrict__ boxes, float* __restrict__ out)
{
    __shared__ float4 sI[32 * 2];
    __shared__ float4 sJ[64 * 2];
    __shared__ float  smT[64][33];              // [jloc][iloc]
    __shared__ unsigned short s_wwl[8][256];    // per-warp worklists

    // linear bid -> (ct, rt) over tiles with rt <= 2*ct+1
    const int b = blockIdx.x;
    int ct = (int)(0.5f * (sqrtf(4.0f * (float)b + 1.0f) - 1.0f));
    if ((ct + 1) * (ct + 2) <= b) ct++;
    if (ct * (ct + 1) > b) ct--;
    const int rt = b - ct * (ct + 1);

    const int ti = rt * 32;
    const int tj = ct * 64;
    const int t  = threadIdx.x;

    // Build SAT data for this tile's 96 boxes
    if (t < 96) {
        const int isJ = (t >= 32);
        const int loc = isJ ? (t - 32) : t;
        const int gb  = isJ ? (tj + loc) : (ti + loc);
        const float* bp = boxes + gb * 5;
        float cx = bp[0], cy = bp[1], w = bp[2], h = bp[3], ang = bp[4];
        float s, c;
        __sincosf(ang, &s, &c);
        float4 v0 = make_float4(cx, cy, w * c, -w * s);
        float4 v1 = make_float4(h * s, h * c, w * w, h * h);
        if (isJ) { sJ[loc * 2] = v0; sJ[loc * 2 + 1] = v1; }
        else     { sI[loc * 2] = v0; sI[loc * 2 + 1] = v1; }
    }
    __syncthreads();

    const int tx = t & 31;
    const int ty = t >> 5;
    const bool diagTile = (rt >= 2 * ct);
    const unsigned lmask_lt = (1u << tx) - 1u;
    unsigned short* const mywl = &s_wwl[ty][0];

    float4 Ja[2], Jb[2];
#pragma unroll
    for (int jj = 0; jj < 2; jj++) {
        int jl = tx + jj * 32;
        Ja[jj] = sJ[jl * 2 + 0];
        Jb[jj] = sJ[jl * 2 + 1];
    }

    // ---- Phase 1: fast separation test; store 0; warp-local compaction ----
    int wcnt = 0;   // uniform across the warp
#pragma unroll
    for (int ii = 0; ii < 4; ii++) {
        const int iloc = ty * 4 + ii;
        const float4 Ia = sI[iloc * 2 + 0];
        const float4 Ib = sI[iloc * 2 + 1];
        float* orow = out + (size_t)(ti + iloc) * NB + tj + tx;
        float* trow = &smT[tx][iloc];

#pragma unroll
        for (int jj = 0; jj < 2; jj++) {
            const int jloc = tx + jj * 32;
            const float a0ix = Ia.z, a0iy = Ia.w, a1ix = Ib.x, a1iy = Ib.y;
            const float a0jx = Ja[jj].z, a0jy = Ja[jj].w;
            const float a1jx = Jb[jj].x, a1jy = Jb[jj].y;

            float dcx = Ja[jj].x - Ia.x;
            float dcy = Ja[jj].y - Ia.y;

            float M00 = fmaf(a0ix, a0jx, a0iy * a0jy);
            float M01 = fmaf(a0ix, a1jx, a0iy * a1jy);
            float M10 = fmaf(a1ix, a0jx, a1iy * a0jy);
            float M11 = fmaf(a1ix, a1jx, a1iy * a1jy);

            float dA0 = fmaf(dcx, a0ix, dcy * a0iy);
            float dA1 = fmaf(dcx, a1ix, dcy * a1iy);
            float dB0 = fmaf(dcx, a0jx, dcy * a0jy);
            float dB1 = fmaf(dcx, a1jx, dcy * a1jy);

            float S0 = Ib.z     + (fabsf(M00) + fabsf(M01));
            float S1 = Ib.w     + (fabsf(M10) + fabsf(M11));
            float S2 = Jb[jj].z + (fabsf(M00) + fabsf(M10));
            float S3 = Jb[jj].w + (fabsf(M01) + fabsf(M11));

            float t0 = fmaf(0.5f, S0, -fabsf(dA0));
            float t1 = fmaf(0.5f, S1, -fabsf(dA1));
            float t2 = fmaf(0.5f, S2, -fabsf(dB0));
            float t3 = fmaf(0.5f, S3, -fabsf(dB1));
            float m = fminf(fminf(t0, t1), fminf(t2, t3));

            bool push = (m > 0.0f);
            if (diagTile && (ti + iloc == tj + jloc)) push = false;

            // default 0 for every pair; overlaps overwritten in phase 2
            orow[jj * 32] = 0.0f;
            trow[jj * 32 * 33] = 0.0f;

            unsigned msk = __ballot_sync(0xffffffffu, push);
            if (push) {
                int pos = wcnt + __popc(msk & lmask_lt);
                mywl[pos] = (unsigned short)(iloc | (jloc << 8));
            }
            wcnt += __popc(msk);
        }
    }
    __syncwarp();

    // ---- Phase 2: dense giou on this warp's worklist ----
    for (int k = tx; k < wcnt; k += 32) {
        const int e = mywl[k];
        const int iloc = e & 255;
        const int jloc = e >> 8;
        const float4 Ia  = sI[iloc * 2 + 0];
        const float4 Ib  = sI[iloc * 2 + 1];
        const float4 Jav = sJ[jloc * 2 + 0];
        const float4 Jbv = sJ[jloc * 2 + 1];

        const float a0ix = Ia.z, a0iy = Ia.w, a1ix = Ib.x, a1iy = Ib.y;
        const float a0jx = Jav.z, a0jy = Jav.w, a1jx = Jbv.x, a1jy = Jbv.y;

        float dcx = Jav.x - Ia.x;
        float dcy = Jav.y - Ia.y;

        float M00 = fmaf(a0ix, a0jx, a0iy * a0jy);
        float M01 = fmaf(a0ix, a1jx, a0iy * a1jy);
        float M10 = fmaf(a1ix, a0jx, a1iy * a0jy);
        float M11 = fmaf(a1ix, a1jx, a1iy * a1jy);

        float dA0 = fmaf(dcx, a0ix, dcy * a0iy);
        float dA1 = fmaf(dcx, a1ix, dcy * a1iy);
        float dB0 = fmaf(dcx, a0jx, dcy * a0jy);
        float dB1 = fmaf(dcx, a1jx, dcy * a1jy);

        float LbA0 = fabsf(M00) + fabsf(M01);
        float LbA1 = fabsf(M10) + fabsf(M11);
        float LbB0 = fabsf(M00) + fabsf(M10);
        float LbB1 = fabsf(M01) + fabsf(M11);

        float S0 = Ib.z  + LbA0;
        float S1 = Ib.w  + LbA1;
        float S2 = Jbv.z + LbB0;
        float S3 = Jbv.w + LbB1;

        float t0 = fmaf(0.5f, S0, -fabsf(dA0));
        float t1 = fmaf(0.5f, S1, -fabsf(dA1));
        float t2 = fmaf(0.5f, S2, -fabsf(dB0));
        float t3 = fmaf(0.5f, S3, -fabsf(dB1));

        float g0 = giou_slow(Ib.z,  LbA0, S0, t0, dA0);
        float g1 = giou_slow(Ib.w,  LbA1, S1, t1, dA1);
        float g2 = giou_slow(Jbv.z, LbB0, S2, t2, dB0);
        float g3 = giou_slow(Jbv.w, LbB1, S3, t3, dB1);

        float res = fmaxf(fminf(fminf(g0, g1), fminf(g2, g3)), 0.0f);
        out[(size_t)(ti + iloc) * NB + tj + jloc] = res;
        smT[jloc][iloc] = res;
    }

    __syncthreads();

    // mirror: out[tj+r][ti + lane], one full row per warp-STG (coalesced)
#pragma unroll
    for (int rr = 0; rr < 8; rr++) {
        int r = ty * 8 + rr;
        out[(size_t)(tj + r) * NB + ti + tx] = smT[r][tx];
    }
}

extern "C" void kernel_launch(void* const* d_in, const int* in_sizes, int n_in,
                              void* d_out, int out_size) {
    const float* boxes = (const float*)d_in[0];
    float* out = (float*)d_out;
    (void)in_sizes; (void)n_in; (void)out_size;

    pair_kernel<<<4160, 256>>>(boxes, out);
}

// round 13
// speedup vs baseline: 1.8278x; 1.3550x over previous
#include <cuda_runtime.h>
#include <math.h>

#define NB 4096

// Per-box SAT data in smem: 2 float4 per box
//  v0 = (cx, cy, a0x, a0y)   center + edge vector 0
//  v1 = (a1x, a1y, L0, L1)   edge vector 1, L = |a|^2
// plus per-box enclosing-circle radius R = 0.5*sqrt(w^2+h^2)

__device__ __forceinline__ float giou_eval(float La, float Lb, float S,
                                           float t_in, float d) {
    float th    = fmaf(0.5f, S, fabsf(d));
    float inter = fminf(fminf(La, Lb), t_in);
    float hull  = fmaxf(fmaxf(La, Lb), th);
    float uni   = S - inter;          // > 0 even if t_in <= 0
    float tmp   = fmaf(2.0f, inter, -S);   // inter - uni
    float N     = fmaf(uni, uni, tmp * hull);
    return __fdividef(N, uni * hull);
}

__global__ __launch_bounds__(256) void pair_kernel(
    const float* __restrict__ boxes, float* __restrict__ out)
{
    __shared__ float4 sI[32 * 2];
    __shared__ float4 sJ[64 * 2];
    __shared__ float  sRI[32];
    __shared__ float  sRJ[64];
    __shared__ float  smT[64][33];              // [jloc][iloc]
    __shared__ unsigned short s_wwl[8][256];    // per-warp worklists

    // linear bid -> (ct, rt) over tiles with rt <= 2*ct+1
    const int b = blockIdx.x;
    int ct = (int)(0.5f * (sqrtf(4.0f * (float)b + 1.0f) - 1.0f));
    if ((ct + 1) * (ct + 2) <= b) ct++;
    if (ct * (ct + 1) > b) ct--;
    const int rt = b - ct * (ct + 1);

    const int ti = rt * 32;
    const int tj = ct * 64;
    const int t  = threadIdx.x;

    // Build SAT data + radius for this tile's 96 boxes
    if (t < 96) {
        const int isJ = (t >= 32);
        const int loc = isJ ? (t - 32) : t;
        const int gb  = isJ ? (tj + loc) : (ti + loc);
        const float* bp = boxes + gb * 5;
        float cx = bp[0], cy = bp[1], w = bp[2], h = bp[3], ang = bp[4];
        float s, c;
        __sincosf(ang, &s, &c);
        float4 v0 = make_float4(cx, cy, w * c, -w * s);
        float4 v1 = make_float4(h * s, h * c, w * w, h * h);
        float R = 0.5f * sqrtf(fmaf(w, w, h * h));
        if (isJ) { sJ[loc * 2] = v0; sJ[loc * 2 + 1] = v1; sRJ[loc] = R; }
        else     { sI[loc * 2] = v0; sI[loc * 2 + 1] = v1; sRI[loc] = R; }
    }
    __syncthreads();

    const int tx = t & 31;
    const int ty = t >> 5;
    const bool diagTile = (rt >= 2 * ct);
    const unsigned lmask_lt = (1u << tx) - 1u;
    unsigned short* const mywl = &s_wwl[ty][0];

    // j-side circle data in registers
    float Jcx[2], Jcy[2], Rj[2];
#pragma unroll
    for (int jj = 0; jj < 2; jj++) {
        int jl = tx + jj * 32;
        float4 v = sJ[jl * 2];
        Jcx[jj] = v.x; Jcy[jj] = v.y;
        Rj[jj] = sRJ[jl];
    }

    // ---- Phase 1: circumradius prefilter; store 0; warp-local compaction ----
    int wcnt = 0;   // uniform across the warp
#pragma unroll
    for (int ii = 0; ii < 4; ii++) {
        const int iloc = ty * 4 + ii;
        const float4 Iv = sI[iloc * 2];
        const float Ri = sRI[iloc];
        float* orow = out + (size_t)(ti + iloc) * NB + tj + tx;
        float* trow = &smT[tx][iloc];

#pragma unroll
        for (int jj = 0; jj < 2; jj++) {
            const int jloc = tx + jj * 32;
            float dcx = Jcx[jj] - Iv.x;
            float dcy = Jcy[jj] - Iv.y;
            float rs  = Ri + Rj[jj];
            float n2  = fmaf(dcx, dcx, dcy * dcy);
            bool push = fmaf(rs, rs, -n2) > 0.0f;   // circles overlap -> candidate
            if (diagTile && (ti + iloc == tj + jloc)) push = false;

            orow[jj * 32] = 0.0f;
            trow[jj * 32 * 33] = 0.0f;

            unsigned msk = __ballot_sync(0xffffffffu, push);
            if (push) {
                int pos = wcnt + __popc(msk & lmask_lt);
                mywl[pos] = (unsigned short)(iloc | (jloc << 8));
            }
            wcnt += __popc(msk);
        }
    }
    __syncwarp();

    // ---- Phase 2: dense SAT + giou on this warp's worklist ----
    for (int k = tx; k < wcnt; k += 32) {
        const int e = mywl[k];
        const int iloc = e & 255;
        const int jloc = e >> 8;
        const float4 Ia  = sI[iloc * 2 + 0];
        const float4 Ib  = sI[iloc * 2 + 1];
        const float4 Jav = sJ[jloc * 2 + 0];
        const float4 Jbv = sJ[jloc * 2 + 1];

        const float a0ix = Ia.z, a0iy = Ia.w, a1ix = Ib.x, a1iy = Ib.y;
        const float a0jx = Jav.z, a0jy = Jav.w, a1jx = Jbv.x, a1jy = Jbv.y;

        float dcx = Jav.x - Ia.x;
        float dcy = Jav.y - Ia.y;

        float M00 = fmaf(a0ix, a0jx, a0iy * a0jy);
        float M01 = fmaf(a0ix, a1jx, a0iy * a1jy);
        float M10 = fmaf(a1ix, a0jx, a1iy * a0jy);
        float M11 = fmaf(a1ix, a1jx, a1iy * a1jy);

        float dA0 = fmaf(dcx, a0ix, dcy * a0iy);
        float dA1 = fmaf(dcx, a1ix, dcy * a1iy);
        float dB0 = fmaf(dcx, a0jx, dcy * a0jy);
        float dB1 = fmaf(dcx, a1jx, dcy * a1jy);

        float LbA0 = fabsf(M00) + fabsf(M01);
        float LbA1 = fabsf(M10) + fabsf(M11);
        float LbB0 = fabsf(M00) + fabsf(M10);
        float LbB1 = fabsf(M01) + fabsf(M11);

        float S0 = Ib.z  + LbA0;
        float S1 = Ib.w  + LbA1;
        float S2 = Jbv.z + LbB0;
        float S3 = Jbv.w + LbB1;

        float t0 = fmaf(0.5f, S0, -fabsf(dA0));
        float t1 = fmaf(0.5f, S1, -fabsf(dA1));
        float t2 = fmaf(0.5f, S2, -fabsf(dB0));
        float t3 = fmaf(0.5f, S3, -fabsf(dB1));
        float m = fminf(fminf(t0, t1), fminf(t2, t3));

        float g0 = giou_eval(Ib.z,  LbA0, S0, t0, dA0);
        float g1 = giou_eval(Ib.w,  LbA1, S1, t1, dA1);
        float g2 = giou_eval(Jbv.z, LbB0, S2, t2, dB0);
        float g3 = giou_eval(Jbv.w, LbB1, S3, t3, dB1);

        float gmin = fminf(fminf(g0, g1), fminf(g2, g3));
        float res = (m > 0.0f) ? fmaxf(gmin, 0.0f) : 0.0f;

        out[(size_t)(ti + iloc) * NB + tj + jloc] = res;
        smT[jloc][iloc] = res;
    }

    __syncthreads();

    // mirror: out[tj+r][ti + lane], one full row per warp-STG (coalesced)
#pragma unroll
    for (int rr = 0; rr < 8; rr++) {
        int r = ty * 8 + rr;
        out[(size_t)(tj + r) * NB + ti + tx] = smT[r][tx];
    }
}

extern "C" void kernel_launch(void* const* d_in, const int* in_sizes, int n_in,
                              void* d_out, int out_size) {
    const float* boxes = (const float*)d_in[0];
    float* out = (float*)d_out;
    (void)in_sizes; (void)n_in; (void)out_size;

    pair_kernel<<<4160, 256>>>(boxes, out);
}